// round 14
// baseline (speedup 1.0000x reference)
#include <cuda_runtime.h>
#include <cuda_bf16.h>
#include <cstdint>

typedef unsigned int uint;

#define NB      1024
#define NIT     100000
#define NCL     10
#define DD      64
#define CH      128                  // items per chunk
#define NCH     782                  // NP / CH
#define NP      (NCH*CH)             // 100096
#define NS      36                   // item splits (contiguous ranges)
#define CPS     22                   // chunks per CTA
#define BT      128                  // batch rows per CTA
#define NSC     98                   // sort/scatter blocks
#define GB      256                  // G1 blocks
#define HB      256                  // H blocks
#define PB      391                  // perm blocks
#define SSPAN   1024
#define LOG2E   1.4426950408889634f
#define PITCH   264

// kmain smem (relative to 1024-aligned base): Ah@0 (16K) | B0@16K B1@32K
#define SM_AH   0
#define SM_B0   16384
#define SMEM_KM (49152 + 1024)
#define SMEM_KP (DD*PITCH*2)         // 33792 B, perm staging

// ---------------- device scratch (zero at load; kmain-fin restores) --------
__device__ float  g_G1[NCL*DD];
__device__ float  g_sums[NB*NCL];
__device__ float  g_cntf[NCL];
__device__ int    g_hist[NSC*NCL];
__device__ int    g_coff[NCL+1];
__device__ int    g_dst[NIT];
__device__ int    g_c1;              // hist-done counter
__device__ int    g_c2;              // kmain-done counter
__device__ int    g_c3;              // scatter-done counter
__device__ int    g_c4;              // G1-done counter
__device__ __align__(16) unsigned short g_Hh[NB*DD];
__device__ __align__(16) unsigned short g_W2h[(size_t)NP*DD];   // padding rows stay 0 forever

// ---------------- PTX helpers (sm_80-class baseline ISA) --------------------
__device__ __forceinline__ uint32_t smem_u32(const void* p) {
    uint32_t a;
    asm("{ .reg .u64 t; cvta.to.shared.u64 t, %1; cvt.u32.u64 %0, t; }" : "=r"(a) : "l"(p));
    return a;
}
__device__ __forceinline__ float ex2f(float x) {
    float r; asm("ex2.approx.ftz.f32 %0, %1;" : "=f"(r) : "f"(x)); return r;
}
#define SW128(o) ((o) ^ (((o) >> 3) & 0x70))

__device__ __forceinline__ void cpa16(uint32_t dst, const void* src) {
    asm volatile("cp.async.cg.shared.global [%0], [%1], 16;" :: "r"(dst), "l"(src));
}
#define CPA_COMMIT() asm volatile("cp.async.commit_group;")
#define CPA_WAIT0()  asm volatile("cp.async.wait_group 0;" ::: "memory")
#define CPA_WAIT1()  asm volatile("cp.async.wait_group 1;" ::: "memory")

#define LDSM4(R, A) \
    asm volatile("ldmatrix.sync.aligned.m8n8.x4.shared.b16 {%0,%1,%2,%3}, [%4];" \
        : "=r"((R)[0]), "=r"((R)[1]), "=r"((R)[2]), "=r"((R)[3]) : "r"(A))

__device__ __forceinline__ void mma_bf16(float* c, const uint* a, uint b0, uint b1) {
    asm volatile("mma.sync.aligned.m16n8k16.row.col.f32.bf16.bf16.f32 "
        "{%0,%1,%2,%3}, {%4,%5,%6,%7}, {%8,%9}, {%0,%1,%2,%3};"
        : "+f"(c[0]), "+f"(c[1]), "+f"(c[2]), "+f"(c[3])
        : "r"(a[0]), "r"(a[1]), "r"(a[2]), "r"(a[3]), "r"(b0), "r"(b1));
}

// ===========================================================================
// Kernel 1: kprep — one launch, four block ranges:
//   0..97              : hist -> sync(g_c1) -> scan -> scatter -> signal g_c3
//   98..353            : G1 segment-sum MLP-16 -> signal g_c4
//   354..609           : H = bf16((input@G1)*log2e), spin g_c4 == GB
//   610..1000          : W2 permute, spin g_c3 == NSC
// Deadlock-free: all signaler blocks are wave-1 resident (6 CTAs/SM @320thr).
// ===========================================================================
__global__ void __launch_bounds__(320) kprep(const int* __restrict__ cl,
                                             const float* __restrict__ W1,
                                             const float* __restrict__ W2,
                                             const float* __restrict__ inp) {
    int t = threadIdx.x, lane = t & 31, w = t >> 5;
    int bid = blockIdx.x;

    if (bid >= NSC + GB + HB) {
        // ================= perm phase =================
        if (t >= 256) return;
        __shared__ int ok;
        if (t == 0) {
            while (*(volatile int*)&g_c3 != NSC) __nanosleep(128);
            ok = 1;
        }
        __syncthreads();
        (void)ok;
        __threadfence();
        extern __shared__ unsigned short shh[];
        int pid = bid - (NSC + GB + HB);
        int i = pid * 256 + t;
#pragma unroll 8
        for (int d = 0; d < DD; d++) {
            float x = (i < NIT) ? W2[(size_t)d*NIT + i] : 0.0f;
            shh[d*PITCH + t] = __bfloat16_as_ushort(__float2bfloat16(x));
        }
        __syncthreads();
        if (i >= NIT) return;
        int dp = g_dst[i];
        uint v[32];
#pragma unroll
        for (int j = 0; j < 32; j++)
            v[j] = (uint)shh[(2*j)*PITCH + t] | ((uint)shh[(2*j+1)*PITCH + t] << 16);
        uint4* dh = (uint4*)(g_W2h + (size_t)dp*DD);
#pragma unroll
        for (int q = 0; q < 8; q++) dh[q] = make_uint4(v[4*q], v[4*q+1], v[4*q+2], v[4*q+3]);
        return;
    }

    if (bid >= NSC + GB) {
        // ================= H phase: wait for G1 =================
        if (t >= 256) return;
        __shared__ int ok;
        if (t == 0) {
            while (*(volatile int*)&g_c4 != GB) __nanosleep(128);
            ok = 1;
        }
        __syncthreads();
        (void)ok;
        __threadfence();
        int e = (bid - (NSC + GB)) * 256 + t;   // 0..65535
        int b = e >> 6, d = e & 63;
        float a = 0.0f;
#pragma unroll
        for (int c = 0; c < NCL; c++) a += inp[b*NCL + c] * g_G1[c*DD + d];
        g_Hh[b*DD + d] = __bfloat16_as_ushort(__float2bfloat16(a * LOG2E));
        return;
    }

    if (bid >= NSC) {
        // ================= G1 phase: 16 items in flight ========
        if (t >= 256) return;
        int d = t & 63;
        int stripe = (bid - NSC)*4 + (t >> 6);
        const int ns = GB*4;
        float acc[NCL];
#pragma unroll
        for (int k = 0; k < NCL; k++) acc[k] = 0.0f;
        int i = stripe;
        for (; i + 15*ns < NIT; i += 16*ns) {
            int cc[16]; float wv[16];
#pragma unroll
            for (int j = 0; j < 16; j++) cc[j] = cl[i + j*ns];
#pragma unroll
            for (int j = 0; j < 16; j++) wv[j] = W1[(size_t)(i + j*ns)*DD + d];
#pragma unroll
            for (int k = 0; k < NCL; k++) {
#pragma unroll
                for (int j = 0; j < 16; j++) if (cc[j] == k) acc[k] += wv[j];
            }
        }
        for (; i < NIT; i += ns) {
            int c = cl[i];
            float w0 = W1[(size_t)i*DD + d];
#pragma unroll
            for (int k = 0; k < NCL; k++) if (c == k) acc[k] += w0;
        }
#pragma unroll
        for (int k = 0; k < NCL; k++) atomicAdd(&g_G1[k*DD + d], acc[k]);
        __syncthreads();
        if (t == 0) { __threadfence(); atomicAdd(&g_c4, 1); }
        return;
    }

    // ================= hist -> scan -> scatter =================
    __shared__ int h[NCL];
    if (t < NCL) h[t] = 0;
    __syncthreads();
    int base = bid * SSPAN;
    if (t < 256) {
        int cnt[NCL];
#pragma unroll
        for (int k = 0; k < NCL; k++) cnt[k] = 0;
#pragma unroll
        for (int q = 0; q < 4; q++) {
            int i = base + q*256 + t;
            if (i < NIT) {
                int c = cl[i];
#pragma unroll
                for (int k = 0; k < NCL; k++) if (c == k) cnt[k]++;
            }
        }
#pragma unroll
        for (int k = 0; k < NCL; k++) if (cnt[k]) atomicAdd(&h[k], cnt[k]);
    }
    __syncthreads();
    if (t < NCL) g_hist[bid*NCL + t] = h[t];
    __threadfence();
    __syncthreads();
    if (t == 0) {
        atomicAdd(&g_c1, 1);
        while (*(volatile int*)&g_c1 != NSC) __nanosleep(64);
    }
    __syncthreads();

    __shared__ int run[NCL];
    __shared__ int wc[8][NCL];
    __shared__ int tot_s[NCL], pre_s[NCL];
    if (w < NCL) {
        int c = w, full = 0, pre = 0;
        for (int b = lane; b < NSC; b += 32) {
            int v = g_hist[b*NCL + c];
            full += v;
            if (b < bid) pre += v;
        }
#pragma unroll
        for (int o = 16; o; o >>= 1) {
            full += __shfl_xor_sync(~0u, full, o);
            pre  += __shfl_xor_sync(~0u, pre,  o);
        }
        if (!lane) { tot_s[c] = full; pre_s[c] = pre; }
    }
    __syncthreads();
    if (t == 0) {
        int r = 0;
        for (int k = 0; k < NCL; k++) {
            int o = r; r += tot_s[k];
            run[k] = o + pre_s[k];
            if (bid == 0) { g_coff[k] = o; g_cntf[k] = (float)tot_s[k]; }
        }
        if (bid == 0) g_coff[NCL] = r;
    }
    __syncthreads();

    unsigned ltm = (1u << lane) - 1u;
    for (int q = 0; q < 4; q++) {
        if (t < 80) ((int*)wc)[t] = 0;
        __syncthreads();
        int i = base + q*256 + t;
        int c = (t < 256 && i < NIT) ? cl[i] : -1;
        unsigned mm = __match_any_sync(0xffffffffu, c);
        int myrank = __popc(mm & ltm);
        if (c >= 0 && myrank == 0) wc[w][c] = __popc(mm);
        __syncthreads();
        if (t < NCL) {
            int k = t, s = run[k];
            for (int ww = 0; ww < 8; ww++) { int tmp = wc[ww][k]; wc[ww][k] = s; s += tmp; }
            run[k] = s;
        }
        __syncthreads();
        if (c >= 0) g_dst[i] = wc[w][c] + myrank;
        __syncthreads();
    }
    __threadfence();
    __syncthreads();
    if (t == 0) atomicAdd(&g_c3, 1);
}

// ===========================================================================
// Kernel 2: kmain — R8 structure: BT=128, 256 thr, 8 warps x (16 rows x 128
// items), quarter-pipelined; A staged from precomputed g_Hh. + fused finalize.
// ===========================================================================
__device__ __forceinline__ void stage_B(uint32_t sb, int buf, int ch, int t) {
    uint32_t bh = sb + SM_B0 + buf*16384;
    const char* gh = (const char*)g_W2h + (size_t)ch*CH*128;
#pragma unroll
    for (int q = 0; q < 4; q++) {
        int off = (t + q*256) * 16;
        cpa16(bh + SW128(off), gh + off);
    }
}

// MMA for one 32-item quarter (2 n-tile-pairs) into acc[4][4]
__device__ __forceinline__ void mma_quarter(float (*acc)[4], const uint (*ah)[4],
                                            uint32_t bbh, const int* bx, int q) {
#pragma unroll
    for (int nt = 0; nt < 4; nt++)
#pragma unroll
        for (int j = 0; j < 4; j++) acc[nt][j] = 0.0f;
#pragma unroll
    for (int ks = 0; ks < 4; ks++) {
#pragma unroll
        for (int j = 0; j < 2; j++) {
            uint r[4];
            LDSM4(r, bbh + (2*q + j)*2048 + bx[ks]);
            mma_bf16(acc[2*j],   ah[ks], r[0], r[1]);
            mma_bf16(acc[2*j+1], ah[ks], r[2], r[3]);
        }
    }
}

// exp2 + segment accumulate for one 32-item quarter
__device__ __forceinline__ void epi_quarter(const float (*acc)[4], int p0base, int bpos,
                                            bool fast, int qd,
                                            float& s0a, float& s0b, float& s1a, float& s1b) {
    if (fast) {
        float ta = 0.f, tb = 0.f;
#pragma unroll
        for (int nt = 0; nt < 4; nt++) {
            ta += ex2f(acc[nt][0]); ta += ex2f(acc[nt][1]);
            tb += ex2f(acc[nt][2]); tb += ex2f(acc[nt][3]);
        }
        s0a += ta; s0b += tb;
    } else {
#pragma unroll
        for (int nt = 0; nt < 4; nt++) {
            float e0 = ex2f(acc[nt][0]), e1 = ex2f(acc[nt][1]);
            float e2 = ex2f(acc[nt][2]), e3 = ex2f(acc[nt][3]);
            int p0 = p0base + nt*8 + qd;
            if (p0 < bpos)          { s0a += e0; s0b += e2; }
            else if (p0 < NIT)      { s1a += e0; s1b += e2; }
            if (p0 + 1 < bpos)      { s0a += e1; s0b += e3; }
            else if (p0 + 1 < NIT)  { s1a += e1; s1b += e3; }
        }
    }
}

__global__ void __launch_bounds__(256, 2) kmain(float* __restrict__ out) {
    extern __shared__ char dsm[];
    __shared__ int coff_s[NCL+1];
    __shared__ int slast;
    uint32_t sb0 = smem_u32(dsm);
    uint32_t pad = (1024u - (sb0 & 1023u)) & 1023u;
    uint32_t sb  = sb0 + pad;

    int t = threadIdx.x, lane = t & 31, w = t >> 5;
    int bbase = blockIdx.x * BT;
    int ch_lo = blockIdx.y * CPS;
    int ch_hi = min(ch_lo + CPS, NCH);
    int n = ch_hi - ch_lo;

    if (t < NCL+1) coff_s[t] = g_coff[t];

    // stage A (Hh, 16 KB, SW128) + first B chunk
    {
        const char* gh = (const char*)g_Hh + (size_t)bbase*128;
#pragma unroll
        for (int q = 0; q < 4; q++) {
            int off = (t + q*256) * 16;
            cpa16(sb + SM_AH + SW128(off), gh + off);
        }
    }
    stage_B(sb, 0, ch_lo, t);
    CPA_COMMIT();
    CPA_WAIT0();
    __syncthreads();

    // per-lane ldmatrix B address precompute
    int m  = lane >> 3, rl = lane & 7;
    int rowb = ((m >> 1) << 3) + rl;
    int kadd = m & 1;
    int bx[4];
#pragma unroll
    for (int ks = 0; ks < 4; ks++)
        bx[ks] = rowb*128 + ((ks*32 + kadd*16) ^ (rl*16));

    // A fragments resident in registers for the whole kernel
    uint ah[4][4];
    {
        int arow = w*16 + ((lane >> 3) & 1)*8 + rl;
#pragma unroll
        for (int ks = 0; ks < 4; ks++) {
            int au   = ks*2 + (lane >> 4);
            int aoff = arow*128 + ((au*16) ^ (rl*16));
            LDSM4(ah[ks], sb + SM_AH + aoff);
        }
    }

    int row0 = bbase + w*16 + (lane >> 2);
    int row1 = row0 + 8;
    int qd   = (lane & 3) * 2;
    float s0a = 0.f, s0b = 0.f, s1a = 0.f, s1b = 0.f;
    int cur = 0;
    { int ib = ch_lo * CH; while (coff_s[cur+1] <= ib) cur++; }

    for (int ii = 0; ii < n; ii++) {
        int buf = ii & 1;
        if (ii + 1 < n) { stage_B(sb, buf ^ 1, ch_lo + ii + 1, t); CPA_COMMIT(); CPA_WAIT1(); }
        else            { CPA_WAIT0(); }
        __syncthreads();

        uint32_t bbh = sb + SM_B0 + buf*16384;
        int ibase = (ch_lo + ii) * CH;

        // cluster-boundary flush
        {
            int nc = cur;
            while (coff_s[nc+1] <= ibase) nc++;
            if (nc != cur) {
                atomicAdd(&g_sums[row0*NCL + cur], s0a);
                atomicAdd(&g_sums[row1*NCL + cur], s0b);
                if (cur + 1 < NCL) {
                    atomicAdd(&g_sums[row0*NCL + cur + 1], s1a);
                    atomicAdd(&g_sums[row1*NCL + cur + 1], s1b);
                }
                s0a = s0b = s1a = s1b = 0.f;
                cur = nc;
            }
        }
        int bpos = coff_s[cur+1];
        bool fast = (ibase + CH <= bpos);

        // quarter-pipelined: MMA(q) overlaps EPI(q-1) via independent reg buffers
        float accA[4][4], accB[4][4];
        mma_quarter(accA, ah, bbh, bx, 0);
        mma_quarter(accB, ah, bbh, bx, 1);
        epi_quarter(accA, ibase,      bpos, fast, qd, s0a, s0b, s1a, s1b);
        mma_quarter(accA, ah, bbh, bx, 2);
        epi_quarter(accB, ibase + 32, bpos, fast, qd, s0a, s0b, s1a, s1b);
        mma_quarter(accB, ah, bbh, bx, 3);
        epi_quarter(accA, ibase + 64, bpos, fast, qd, s0a, s0b, s1a, s1b);
        epi_quarter(accB, ibase + 96, bpos, fast, qd, s0a, s0b, s1a, s1b);

        __syncthreads();
    }

    atomicAdd(&g_sums[row0*NCL + cur], s0a);
    atomicAdd(&g_sums[row1*NCL + cur], s0b);
    if (cur + 1 < NCL) {
        atomicAdd(&g_sums[row0*NCL + cur + 1], s1a);
        atomicAdd(&g_sums[row1*NCL + cur + 1], s1b);
    }

    // ---- fused finalize: last CTA computes output + restores scratch -----
    __threadfence();
    __syncthreads();
    if (t == 0) slast = (atomicAdd(&g_c2, 1) == (int)(gridDim.x*gridDim.y) - 1);
    __syncthreads();
    if (slast) {
        __threadfence();
        for (int b = t; b < NB; b += 256) {
            float v[NCL], z = 0.0f;
#pragma unroll
            for (int c = 0; c < NCL; c++) { v[c] = g_sums[b*NCL + c]; z += v[c]; }
            float invz = 1.0f / z;
#pragma unroll
            for (int c = 0; c < NCL; c++)
                out[b*NCL + c] = v[c] * invz / fmaxf(g_cntf[c], 1.0f);
#pragma unroll
            for (int c = 0; c < NCL; c++) g_sums[b*NCL + c] = 0.0f;
        }
        for (int i = t; i < NCL*DD; i += 256) g_G1[i] = 0.0f;
        if (t == 0) { g_c1 = 0; g_c2 = 0; g_c3 = 0; g_c4 = 0; }
    }
}

// ---------------------------------------------------------------------------
extern "C" void kernel_launch(void* const* d_in, const int* in_sizes, int n_in,
                              void* d_out, int out_size) {
    const float* input = (const float*)d_in[0];   // (1024, 10) f32
    const int*   clust = (const int*)d_in[1];     // (100000,) i32
    const float* W1    = (const float*)d_in[2];   // (100000, 64) f32
    const float* W2    = (const float*)d_in[3];   // (64, 100000) f32
    float*       out   = (float*)d_out;           // (1024, 10) f32

    cudaFuncSetAttribute(kmain, cudaFuncAttributeMaxDynamicSharedMemorySize, SMEM_KM);
    cudaFuncSetAttribute(kprep, cudaFuncAttributeMaxDynamicSharedMemorySize, SMEM_KP);

    kprep<<<NSC + GB + HB + PB, 320, SMEM_KP>>>(clust, W1, W2, input);
    dim3 grid(NB / BT, NS);
    kmain<<<grid, 256, SMEM_KM>>>(out);
}

// round 15
// speedup vs baseline: 1.0217x; 1.0217x over previous
#include <cuda_runtime.h>
#include <cuda_bf16.h>
#include <cstdint>

typedef unsigned int uint;

#define NB      1024
#define NIT     100000
#define NCL     10
#define DD      64
#define CH      128                  // items per chunk
#define NCH     782                  // NP / CH
#define NP      (NCH*CH)             // 100096
#define NS      36                   // item splits (contiguous ranges)
#define CPS     22                   // chunks per CTA
#define BT      128                  // batch rows per CTA
#define NSC     98                   // sort/scatter blocks
#define GB      256                  // G1 blocks
#define HB      256                  // H blocks
#define PB      391                  // perm blocks
#define SSPAN   1024
#define LOG2E   1.4426950408889634f
#define PITCH   264

// kmain smem (relative to 1024-aligned base): Ah@0 (16K) | B0@16K B1@32K
#define SM_AH   0
#define SM_B0   16384
#define SMEM_KM (49152 + 1024)
#define SMEM_KP (DD*PITCH*2)         // 33792 B, perm staging

// ---------------- device scratch (zero at load; kmain-fin restores) --------
__device__ float  g_G1[NCL*DD];
__device__ float  g_sums[NB*NCL];
__device__ float  g_cntf[NCL];
__device__ int    g_hist[NSC*NCL];
__device__ int    g_coff[NCL+1];
__device__ int    g_dst[NIT];
__device__ int    g_c1;              // hist-done counter
__device__ int    g_c2;              // kmain-done counter
__device__ int    g_c3;              // scatter-done counter
__device__ int    g_c4;              // G1-done counter
__device__ __align__(16) unsigned short g_Hh[NB*DD];
__device__ __align__(16) unsigned short g_W2h[(size_t)NP*DD];   // padding rows stay 0 forever

// ---------------- PTX helpers (sm_80-class baseline ISA) --------------------
__device__ __forceinline__ uint32_t smem_u32(const void* p) {
    uint32_t a;
    asm("{ .reg .u64 t; cvta.to.shared.u64 t, %1; cvt.u32.u64 %0, t; }" : "=r"(a) : "l"(p));
    return a;
}
__device__ __forceinline__ float ex2f(float x) {
    float r; asm("ex2.approx.ftz.f32 %0, %1;" : "=f"(r) : "f"(x)); return r;
}
#define SW128(o) ((o) ^ (((o) >> 3) & 0x70))

__device__ __forceinline__ void cpa16(uint32_t dst, const void* src) {
    asm volatile("cp.async.cg.shared.global [%0], [%1], 16;" :: "r"(dst), "l"(src));
}
#define CPA_COMMIT() asm volatile("cp.async.commit_group;")
#define CPA_WAIT0()  asm volatile("cp.async.wait_group 0;" ::: "memory")
#define CPA_WAIT1()  asm volatile("cp.async.wait_group 1;" ::: "memory")

#define LDSM4(R, A) \
    asm volatile("ldmatrix.sync.aligned.m8n8.x4.shared.b16 {%0,%1,%2,%3}, [%4];" \
        : "=r"((R)[0]), "=r"((R)[1]), "=r"((R)[2]), "=r"((R)[3]) : "r"(A))

__device__ __forceinline__ void mma_bf16(float* c, const uint* a, uint b0, uint b1) {
    asm volatile("mma.sync.aligned.m16n8k16.row.col.f32.bf16.bf16.f32 "
        "{%0,%1,%2,%3}, {%4,%5,%6,%7}, {%8,%9}, {%0,%1,%2,%3};"
        : "+f"(c[0]), "+f"(c[1]), "+f"(c[2]), "+f"(c[3])
        : "r"(a[0]), "r"(a[1]), "r"(a[2]), "r"(a[3]), "r"(b0), "r"(b1));
}

// ===========================================================================
// Kernel 1: kprep — one launch, four block ranges (unchanged from R14)
// ===========================================================================
__global__ void __launch_bounds__(320) kprep(const int* __restrict__ cl,
                                             const float* __restrict__ W1,
                                             const float* __restrict__ W2,
                                             const float* __restrict__ inp) {
    int t = threadIdx.x, lane = t & 31, w = t >> 5;
    int bid = blockIdx.x;

    if (bid >= NSC + GB + HB) {
        // ================= perm phase =================
        if (t >= 256) return;
        __shared__ int ok;
        if (t == 0) {
            while (*(volatile int*)&g_c3 != NSC) __nanosleep(128);
            ok = 1;
        }
        __syncthreads();
        (void)ok;
        __threadfence();
        extern __shared__ unsigned short shh[];
        int pid = bid - (NSC + GB + HB);
        int i = pid * 256 + t;
#pragma unroll 8
        for (int d = 0; d < DD; d++) {
            float x = (i < NIT) ? W2[(size_t)d*NIT + i] : 0.0f;
            shh[d*PITCH + t] = __bfloat16_as_ushort(__float2bfloat16(x));
        }
        __syncthreads();
        if (i >= NIT) return;
        int dp = g_dst[i];
        uint v[32];
#pragma unroll
        for (int j = 0; j < 32; j++)
            v[j] = (uint)shh[(2*j)*PITCH + t] | ((uint)shh[(2*j+1)*PITCH + t] << 16);
        uint4* dh = (uint4*)(g_W2h + (size_t)dp*DD);
#pragma unroll
        for (int q = 0; q < 8; q++) dh[q] = make_uint4(v[4*q], v[4*q+1], v[4*q+2], v[4*q+3]);
        return;
    }

    if (bid >= NSC + GB) {
        // ================= H phase: wait for G1 =================
        if (t >= 256) return;
        __shared__ int ok;
        if (t == 0) {
            while (*(volatile int*)&g_c4 != GB) __nanosleep(128);
            ok = 1;
        }
        __syncthreads();
        (void)ok;
        __threadfence();
        int e = (bid - (NSC + GB)) * 256 + t;   // 0..65535
        int b = e >> 6, d = e & 63;
        float a = 0.0f;
#pragma unroll
        for (int c = 0; c < NCL; c++) a += inp[b*NCL + c] * g_G1[c*DD + d];
        g_Hh[b*DD + d] = __bfloat16_as_ushort(__float2bfloat16(a * LOG2E));
        return;
    }

    if (bid >= NSC) {
        // ================= G1 phase: 16 items in flight ========
        if (t >= 256) return;
        int d = t & 63;
        int stripe = (bid - NSC)*4 + (t >> 6);
        const int ns = GB*4;
        float acc[NCL];
#pragma unroll
        for (int k = 0; k < NCL; k++) acc[k] = 0.0f;
        int i = stripe;
        for (; i + 15*ns < NIT; i += 16*ns) {
            int cc[16]; float wv[16];
#pragma unroll
            for (int j = 0; j < 16; j++) cc[j] = cl[i + j*ns];
#pragma unroll
            for (int j = 0; j < 16; j++) wv[j] = W1[(size_t)(i + j*ns)*DD + d];
#pragma unroll
            for (int k = 0; k < NCL; k++) {
#pragma unroll
                for (int j = 0; j < 16; j++) if (cc[j] == k) acc[k] += wv[j];
            }
        }
        for (; i < NIT; i += ns) {
            int c = cl[i];
            float w0 = W1[(size_t)i*DD + d];
#pragma unroll
            for (int k = 0; k < NCL; k++) if (c == k) acc[k] += w0;
        }
#pragma unroll
        for (int k = 0; k < NCL; k++) atomicAdd(&g_G1[k*DD + d], acc[k]);
        __syncthreads();
        if (t == 0) { __threadfence(); atomicAdd(&g_c4, 1); }
        return;
    }

    // ================= hist -> scan -> scatter =================
    __shared__ int h[NCL];
    if (t < NCL) h[t] = 0;
    __syncthreads();
    int base = bid * SSPAN;
    if (t < 256) {
        int cnt[NCL];
#pragma unroll
        for (int k = 0; k < NCL; k++) cnt[k] = 0;
#pragma unroll
        for (int q = 0; q < 4; q++) {
            int i = base + q*256 + t;
            if (i < NIT) {
                int c = cl[i];
#pragma unroll
                for (int k = 0; k < NCL; k++) if (c == k) cnt[k]++;
            }
        }
#pragma unroll
        for (int k = 0; k < NCL; k++) if (cnt[k]) atomicAdd(&h[k], cnt[k]);
    }
    __syncthreads();
    if (t < NCL) g_hist[bid*NCL + t] = h[t];
    __threadfence();
    __syncthreads();
    if (t == 0) {
        atomicAdd(&g_c1, 1);
        while (*(volatile int*)&g_c1 != NSC) __nanosleep(64);
    }
    __syncthreads();

    __shared__ int run[NCL];
    __shared__ int wc[8][NCL];
    __shared__ int tot_s[NCL], pre_s[NCL];
    if (w < NCL) {
        int c = w, full = 0, pre = 0;
        for (int b = lane; b < NSC; b += 32) {
            int v = g_hist[b*NCL + c];
            full += v;
            if (b < bid) pre += v;
        }
#pragma unroll
        for (int o = 16; o; o >>= 1) {
            full += __shfl_xor_sync(~0u, full, o);
            pre  += __shfl_xor_sync(~0u, pre,  o);
        }
        if (!lane) { tot_s[c] = full; pre_s[c] = pre; }
    }
    __syncthreads();
    if (t == 0) {
        int r = 0;
        for (int k = 0; k < NCL; k++) {
            int o = r; r += tot_s[k];
            run[k] = o + pre_s[k];
            if (bid == 0) { g_coff[k] = o; g_cntf[k] = (float)tot_s[k]; }
        }
        if (bid == 0) g_coff[NCL] = r;
    }
    __syncthreads();

    unsigned ltm = (1u << lane) - 1u;
    for (int q = 0; q < 4; q++) {
        if (t < 80) ((int*)wc)[t] = 0;
        __syncthreads();
        int i = base + q*256 + t;
        int c = (t < 256 && i < NIT) ? cl[i] : -1;
        unsigned mm = __match_any_sync(0xffffffffu, c);
        int myrank = __popc(mm & ltm);
        if (c >= 0 && myrank == 0) wc[w][c] = __popc(mm);
        __syncthreads();
        if (t < NCL) {
            int k = t, s = run[k];
            for (int ww = 0; ww < 8; ww++) { int tmp = wc[ww][k]; wc[ww][k] = s; s += tmp; }
            run[k] = s;
        }
        __syncthreads();
        if (c >= 0) g_dst[i] = wc[w][c] + myrank;
        __syncthreads();
    }
    __threadfence();
    __syncthreads();
    if (t == 0) atomicAdd(&g_c3, 1);
}

// ===========================================================================
// Kernel 2: kmain — cross-chunk pipelined HMMA: epi(q2,q3) of chunk i overlap
// MMAs of chunk i+1 via 3 rotating accumulator buffers.
// ===========================================================================
__device__ __forceinline__ void stage_B(uint32_t sb, int buf, int ch, int t) {
    uint32_t bh = sb + SM_B0 + buf*16384;
    const char* gh = (const char*)g_W2h + (size_t)ch*CH*128;
#pragma unroll
    for (int q = 0; q < 4; q++) {
        int off = (t + q*256) * 16;
        cpa16(bh + SW128(off), gh + off);
    }
}

// MMA for one 32-item quarter (2 n-tile-pairs) into acc[4][4]
__device__ __forceinline__ void mma_quarter(float (*acc)[4], const uint (*ah)[4],
                                            uint32_t bbh, const int* bx, int q) {
#pragma unroll
    for (int nt = 0; nt < 4; nt++)
#pragma unroll
        for (int j = 0; j < 4; j++) acc[nt][j] = 0.0f;
#pragma unroll
    for (int ks = 0; ks < 4; ks++) {
#pragma unroll
        for (int j = 0; j < 2; j++) {
            uint r[4];
            LDSM4(r, bbh + (2*q + j)*2048 + bx[ks]);
            mma_bf16(acc[2*j],   ah[ks], r[0], r[1]);
            mma_bf16(acc[2*j+1], ah[ks], r[2], r[3]);
        }
    }
}

// exp2 + segment accumulate for one 32-item quarter
__device__ __forceinline__ void epi_quarter(const float (*acc)[4], int p0base, int bpos,
                                            bool fast, int qd,
                                            float& s0a, float& s0b, float& s1a, float& s1b) {
    if (fast) {
        float ta = 0.f, tb = 0.f;
#pragma unroll
        for (int nt = 0; nt < 4; nt++) {
            ta += ex2f(acc[nt][0]); ta += ex2f(acc[nt][1]);
            tb += ex2f(acc[nt][2]); tb += ex2f(acc[nt][3]);
        }
        s0a += ta; s0b += tb;
    } else {
#pragma unroll
        for (int nt = 0; nt < 4; nt++) {
            float e0 = ex2f(acc[nt][0]), e1 = ex2f(acc[nt][1]);
            float e2 = ex2f(acc[nt][2]), e3 = ex2f(acc[nt][3]);
            int p0 = p0base + nt*8 + qd;
            if (p0 < bpos)          { s0a += e0; s0b += e2; }
            else if (p0 < NIT)      { s1a += e0; s1b += e2; }
            if (p0 + 1 < bpos)      { s0a += e1; s0b += e3; }
            else if (p0 + 1 < NIT)  { s1a += e1; s1b += e3; }
        }
    }
}

#define FLUSH_BOUNDARY(ibase_) do {                                          \
    int nc = cur;                                                            \
    while (coff_s[nc+1] <= (ibase_)) nc++;                                   \
    if (nc != cur) {                                                         \
        atomicAdd(&g_sums[row0*NCL + cur], s0a);                             \
        atomicAdd(&g_sums[row1*NCL + cur], s0b);                             \
        if (cur + 1 < NCL) {                                                 \
            atomicAdd(&g_sums[row0*NCL + cur + 1], s1a);                     \
            atomicAdd(&g_sums[row1*NCL + cur + 1], s1b);                     \
        }                                                                    \
        s0a = s0b = s1a = s1b = 0.f;                                         \
        cur = nc;                                                            \
    }                                                                        \
} while (0)

// steady-state pipelined step: A,B hold pending q2/q3 of previous chunk
#define STEP(A_, B_, C_, II) do {                                            \
    if ((II) + 1 < n) { stage_B(sb, ((II)+1)&1, ch_lo + (II) + 1, t);        \
                        CPA_COMMIT(); CPA_WAIT1(); }                         \
    else              { CPA_WAIT0(); }                                       \
    __syncthreads();                                                         \
    uint32_t bbh = sb + SM_B0 + ((II)&1)*16384;                              \
    int ibase = (ch_lo + (II)) * CH;                                         \
    mma_quarter(C_, ah, bbh, bx, 0);                                         \
    epi_quarter(A_, prev_ibase + 64, prev_bpos, prev_fast, qd, s0a,s0b,s1a,s1b); \
    mma_quarter(A_, ah, bbh, bx, 1);                                         \
    epi_quarter(B_, prev_ibase + 96, prev_bpos, prev_fast, qd, s0a,s0b,s1a,s1b); \
    FLUSH_BOUNDARY(ibase);                                                   \
    int bpos = coff_s[cur+1];                                                \
    bool fast = (ibase + CH <= bpos);                                        \
    mma_quarter(B_, ah, bbh, bx, 2);                                         \
    epi_quarter(C_, ibase, bpos, fast, qd, s0a,s0b,s1a,s1b);                 \
    mma_quarter(C_, ah, bbh, bx, 3);                                         \
    epi_quarter(A_, ibase + 32, bpos, fast, qd, s0a,s0b,s1a,s1b);            \
    prev_ibase = ibase; prev_bpos = bpos; prev_fast = fast;                  \
    __syncthreads();                                                         \
} while (0)
// after STEP(A,B,C): pending = B(q2), C(q3); free = A

__global__ void __launch_bounds__(256, 2) kmain(float* __restrict__ out) {
    extern __shared__ char dsm[];
    __shared__ int coff_s[NCL+1];
    __shared__ int slast;
    uint32_t sb0 = smem_u32(dsm);
    uint32_t pad = (1024u - (sb0 & 1023u)) & 1023u;
    uint32_t sb  = sb0 + pad;

    int t = threadIdx.x, lane = t & 31, w = t >> 5;
    int bbase = blockIdx.x * BT;
    int ch_lo = blockIdx.y * CPS;
    int ch_hi = min(ch_lo + CPS, NCH);
    int n = ch_hi - ch_lo;

    if (t < NCL+1) coff_s[t] = g_coff[t];

    // stage A (Hh, 16 KB, SW128) + first B chunk
    {
        const char* gh = (const char*)g_Hh + (size_t)bbase*128;
#pragma unroll
        for (int q = 0; q < 4; q++) {
            int off = (t + q*256) * 16;
            cpa16(sb + SM_AH + SW128(off), gh + off);
        }
    }
    stage_B(sb, 0, ch_lo, t);
    CPA_COMMIT();
    CPA_WAIT0();
    __syncthreads();

    // per-lane ldmatrix B address precompute
    int m  = lane >> 3, rl = lane & 7;
    int rowb = ((m >> 1) << 3) + rl;
    int kadd = m & 1;
    int bx[4];
#pragma unroll
    for (int ks = 0; ks < 4; ks++)
        bx[ks] = rowb*128 + ((ks*32 + kadd*16) ^ (rl*16));

    // A fragments resident in registers for the whole kernel
    uint ah[4][4];
    {
        int arow = w*16 + ((lane >> 3) & 1)*8 + rl;
#pragma unroll
        for (int ks = 0; ks < 4; ks++) {
            int au   = ks*2 + (lane >> 4);
            int aoff = arow*128 + ((au*16) ^ (rl*16));
            LDSM4(ah[ks], sb + SM_AH + aoff);
        }
    }

    int row0 = bbase + w*16 + (lane >> 2);
    int row1 = row0 + 8;
    int qd   = (lane & 3) * 2;
    float s0a = 0.f, s0b = 0.f, s1a = 0.f, s1b = 0.f;
    int cur = 0;
    { int ib = ch_lo * CH; while (coff_s[cur+1] <= ib) cur++; }

    float acc0[4][4], acc1[4][4], acc2[4][4];
    int prev_ibase, prev_bpos;
    bool prev_fast;

    // ---- iteration 0 (no pending epilogues) ----
    {
        if (1 < n) { stage_B(sb, 1, ch_lo + 1, t); CPA_COMMIT(); CPA_WAIT1(); }
        else       { CPA_WAIT0(); }
        __syncthreads();
        uint32_t bbh = sb + SM_B0;
        int ibase = ch_lo * CH;
        FLUSH_BOUNDARY(ibase);
        int bpos = coff_s[cur+1];
        bool fast = (ibase + CH <= bpos);
        mma_quarter(acc2, ah, bbh, bx, 0);
        mma_quarter(acc0, ah, bbh, bx, 1);
        mma_quarter(acc1, ah, bbh, bx, 2);
        epi_quarter(acc2, ibase, bpos, fast, qd, s0a,s0b,s1a,s1b);        // q0
        mma_quarter(acc2, ah, bbh, bx, 3);                                // q3 -> acc2
        epi_quarter(acc0, ibase + 32, bpos, fast, qd, s0a,s0b,s1a,s1b);   // q1
        prev_ibase = ibase; prev_bpos = bpos; prev_fast = fast;
        __syncthreads();
        // pending: acc1(q2), acc2(q3); free acc0
    }

    // ---- steady state: rotate slots (period 3) ----
    {
        int ii = 1;
        while (ii < n) {
            STEP(acc1, acc2, acc0, ii); ii++;     // -> pending acc2, acc0
            if (ii >= n) break;
            STEP(acc2, acc0, acc1, ii); ii++;     // -> pending acc0, acc1
            if (ii >= n) break;
            STEP(acc0, acc1, acc2, ii); ii++;     // -> pending acc1, acc2
        }
    }

    // ---- drain pending epilogues of the last chunk ----
    {
        int r = (n - 1) % 3;   // number of steps mod 3
        if (r == 0) {
            epi_quarter(acc1, prev_ibase + 64, prev_bpos, prev_fast, qd, s0a,s0b,s1a,s1b);
            epi_quarter(acc2, prev_ibase + 96, prev_bpos, prev_fast, qd, s0a,s0b,s1a,s1b);
        } else if (r == 1) {
            epi_quarter(acc2, prev_ibase + 64, prev_bpos, prev_fast, qd, s0a,s0b,s1a,s1b);
            epi_quarter(acc0, prev_ibase + 96, prev_bpos, prev_fast, qd, s0a,s0b,s1a,s1b);
        } else {
            epi_quarter(acc0, prev_ibase + 64, prev_bpos, prev_fast, qd, s0a,s0b,s1a,s1b);
            epi_quarter(acc1, prev_ibase + 96, prev_bpos, prev_fast, qd, s0a,s0b,s1a,s1b);
        }
    }

    atomicAdd(&g_sums[row0*NCL + cur], s0a);
    atomicAdd(&g_sums[row1*NCL + cur], s0b);
    if (cur + 1 < NCL) {
        atomicAdd(&g_sums[row0*NCL + cur + 1], s1a);
        atomicAdd(&g_sums[row1*NCL + cur + 1], s1b);
    }

    // ---- fused finalize: last CTA computes output + restores scratch -----
    __threadfence();
    __syncthreads();
    if (t == 0) slast = (atomicAdd(&g_c2, 1) == (int)(gridDim.x*gridDim.y) - 1);
    __syncthreads();
    if (slast) {
        __threadfence();
        for (int b = t; b < NB; b += 256) {
            float v[NCL], z = 0.0f;
#pragma unroll
            for (int c = 0; c < NCL; c++) { v[c] = g_sums[b*NCL + c]; z += v[c]; }
            float invz = 1.0f / z;
#pragma unroll
            for (int c = 0; c < NCL; c++)
                out[b*NCL + c] = v[c] * invz / fmaxf(g_cntf[c], 1.0f);
#pragma unroll
            for (int c = 0; c < NCL; c++) g_sums[b*NCL + c] = 0.0f;
        }
        for (int i = t; i < NCL*DD; i += 256) g_G1[i] = 0.0f;
        if (t == 0) { g_c1 = 0; g_c2 = 0; g_c3 = 0; g_c4 = 0; }
    }
}

// ---------------------------------------------------------------------------
extern "C" void kernel_launch(void* const* d_in, const int* in_sizes, int n_in,
                              void* d_out, int out_size) {
    const float* input = (const float*)d_in[0];   // (1024, 10) f32
    const int*   clust = (const int*)d_in[1];     // (100000,) i32
    const float* W1    = (const float*)d_in[2];   // (100000, 64) f32
    const float* W2    = (const float*)d_in[3];   // (64, 100000) f32
    float*       out   = (float*)d_out;           // (1024, 10) f32

    cudaFuncSetAttribute(kmain, cudaFuncAttributeMaxDynamicSharedMemorySize, SMEM_KM);
    cudaFuncSetAttribute(kprep, cudaFuncAttributeMaxDynamicSharedMemorySize, SMEM_KP);

    kprep<<<NSC + GB + HB + PB, 320, SMEM_KP>>>(clust, W1, W2, input);
    dim3 grid(NB / BT, NS);
    kmain<<<grid, 256, SMEM_KM>>>(out);
}

// round 16
// speedup vs baseline: 1.0249x; 1.0031x over previous
#include <cuda_runtime.h>
#include <cuda_bf16.h>
#include <cstdint>

typedef unsigned int uint;

#define NB      1024
#define NIT     100000
#define NCL     10
#define DD      64
#define CH      128                  // items per chunk
#define NCH     782                  // NP / CH
#define NP      (NCH*CH)             // 100096
#define NS      37                   // item splits (balanced; grid 8x37=296=2/SM)
#define BT      128                  // batch rows per CTA
#define NSC     98                   // sort/scatter blocks
#define GB      256                  // G1 blocks
#define HB      256                  // H blocks
#define PB      391                  // perm blocks
#define SSPAN   1024
#define LOG2E   1.4426950408889634f
#define PITCH   264

// kmain smem (relative to 1024-aligned base): Ah@0 (16K) | B0@16K B1@32K
#define SM_AH   0
#define SM_B0   16384
#define SMEM_KM (49152 + 1024)
#define SMEM_KP (DD*PITCH*2)         // 33792 B, perm staging

// ---------------- device scratch (zero at load; kmain-fin restores) --------
__device__ float  g_G1[NCL*DD];
__device__ float  g_sums[NB*NCL];
__device__ float  g_cntf[NCL];
__device__ int    g_hist[NSC*NCL];
__device__ int    g_coff[NCL+1];
__device__ int    g_dst[NIT];
__device__ int    g_c1;              // hist-done counter
__device__ int    g_c2;              // kmain-done counter
__device__ int    g_c3;              // scatter-done counter
__device__ int    g_c4;              // G1-done counter
__device__ __align__(16) unsigned short g_Hh[NB*DD];
__device__ __align__(16) unsigned short g_W2h[(size_t)NP*DD];   // padding rows stay 0 forever

// ---------------- PTX helpers (sm_80-class baseline ISA) --------------------
__device__ __forceinline__ uint32_t smem_u32(const void* p) {
    uint32_t a;
    asm("{ .reg .u64 t; cvta.to.shared.u64 t, %1; cvt.u32.u64 %0, t; }" : "=r"(a) : "l"(p));
    return a;
}
__device__ __forceinline__ float ex2f(float x) {
    float r; asm("ex2.approx.ftz.f32 %0, %1;" : "=f"(r) : "f"(x)); return r;
}
#define SW128(o) ((o) ^ (((o) >> 3) & 0x70))

__device__ __forceinline__ void cpa16(uint32_t dst, const void* src) {
    asm volatile("cp.async.cg.shared.global [%0], [%1], 16;" :: "r"(dst), "l"(src));
}
#define CPA_COMMIT() asm volatile("cp.async.commit_group;")
#define CPA_WAIT0()  asm volatile("cp.async.wait_group 0;" ::: "memory")
#define CPA_WAIT1()  asm volatile("cp.async.wait_group 1;" ::: "memory")

#define LDSM4(R, A) \
    asm volatile("ldmatrix.sync.aligned.m8n8.x4.shared.b16 {%0,%1,%2,%3}, [%4];" \
        : "=r"((R)[0]), "=r"((R)[1]), "=r"((R)[2]), "=r"((R)[3]) : "r"(A))

__device__ __forceinline__ void mma_bf16(float* c, const uint* a, uint b0, uint b1) {
    asm volatile("mma.sync.aligned.m16n8k16.row.col.f32.bf16.bf16.f32 "
        "{%0,%1,%2,%3}, {%4,%5,%6,%7}, {%8,%9}, {%0,%1,%2,%3};"
        : "+f"(c[0]), "+f"(c[1]), "+f"(c[2]), "+f"(c[3])
        : "r"(a[0]), "r"(a[1]), "r"(a[2]), "r"(a[3]), "r"(b0), "r"(b1));
}

// ===========================================================================
// Kernel 1: kprep — one launch, four block ranges (unchanged from R15)
// ===========================================================================
__global__ void __launch_bounds__(320) kprep(const int* __restrict__ cl,
                                             const float* __restrict__ W1,
                                             const float* __restrict__ W2,
                                             const float* __restrict__ inp) {
    int t = threadIdx.x, lane = t & 31, w = t >> 5;
    int bid = blockIdx.x;

    if (bid >= NSC + GB + HB) {
        // ================= perm phase =================
        if (t >= 256) return;
        __shared__ int ok;
        if (t == 0) {
            while (*(volatile int*)&g_c3 != NSC) __nanosleep(128);
            ok = 1;
        }
        __syncthreads();
        (void)ok;
        __threadfence();
        extern __shared__ unsigned short shh[];
        int pid = bid - (NSC + GB + HB);
        int i = pid * 256 + t;
#pragma unroll 8
        for (int d = 0; d < DD; d++) {
            float x = (i < NIT) ? W2[(size_t)d*NIT + i] : 0.0f;
            shh[d*PITCH + t] = __bfloat16_as_ushort(__float2bfloat16(x));
        }
        __syncthreads();
        if (i >= NIT) return;
        int dp = g_dst[i];
        uint v[32];
#pragma unroll
        for (int j = 0; j < 32; j++)
            v[j] = (uint)shh[(2*j)*PITCH + t] | ((uint)shh[(2*j+1)*PITCH + t] << 16);
        uint4* dh = (uint4*)(g_W2h + (size_t)dp*DD);
#pragma unroll
        for (int q = 0; q < 8; q++) dh[q] = make_uint4(v[4*q], v[4*q+1], v[4*q+2], v[4*q+3]);
        return;
    }

    if (bid >= NSC + GB) {
        // ================= H phase: wait for G1 =================
        if (t >= 256) return;
        __shared__ int ok;
        if (t == 0) {
            while (*(volatile int*)&g_c4 != GB) __nanosleep(128);
            ok = 1;
        }
        __syncthreads();
        (void)ok;
        __threadfence();
        int e = (bid - (NSC + GB)) * 256 + t;   // 0..65535
        int b = e >> 6, d = e & 63;
        float a = 0.0f;
#pragma unroll
        for (int c = 0; c < NCL; c++) a += inp[b*NCL + c] * g_G1[c*DD + d];
        g_Hh[b*DD + d] = __bfloat16_as_ushort(__float2bfloat16(a * LOG2E));
        return;
    }

    if (bid >= NSC) {
        // ================= G1 phase: 16 items in flight ========
        if (t >= 256) return;
        int d = t & 63;
        int stripe = (bid - NSC)*4 + (t >> 6);
        const int ns = GB*4;
        float acc[NCL];
#pragma unroll
        for (int k = 0; k < NCL; k++) acc[k] = 0.0f;
        int i = stripe;
        for (; i + 15*ns < NIT; i += 16*ns) {
            int cc[16]; float wv[16];
#pragma unroll
            for (int j = 0; j < 16; j++) cc[j] = cl[i + j*ns];
#pragma unroll
            for (int j = 0; j < 16; j++) wv[j] = W1[(size_t)(i + j*ns)*DD + d];
#pragma unroll
            for (int k = 0; k < NCL; k++) {
#pragma unroll
                for (int j = 0; j < 16; j++) if (cc[j] == k) acc[k] += wv[j];
            }
        }
        for (; i < NIT; i += ns) {
            int c = cl[i];
            float w0 = W1[(size_t)i*DD + d];
#pragma unroll
            for (int k = 0; k < NCL; k++) if (c == k) acc[k] += w0;
        }
#pragma unroll
        for (int k = 0; k < NCL; k++) atomicAdd(&g_G1[k*DD + d], acc[k]);
        __syncthreads();
        if (t == 0) { __threadfence(); atomicAdd(&g_c4, 1); }
        return;
    }

    // ================= hist -> scan -> scatter =================
    __shared__ int h[NCL];
    if (t < NCL) h[t] = 0;
    __syncthreads();
    int base = bid * SSPAN;
    if (t < 256) {
        int cnt[NCL];
#pragma unroll
        for (int k = 0; k < NCL; k++) cnt[k] = 0;
#pragma unroll
        for (int q = 0; q < 4; q++) {
            int i = base + q*256 + t;
            if (i < NIT) {
                int c = cl[i];
#pragma unroll
                for (int k = 0; k < NCL; k++) if (c == k) cnt[k]++;
            }
        }
#pragma unroll
        for (int k = 0; k < NCL; k++) if (cnt[k]) atomicAdd(&h[k], cnt[k]);
    }
    __syncthreads();
    if (t < NCL) g_hist[bid*NCL + t] = h[t];
    __threadfence();
    __syncthreads();
    if (t == 0) {
        atomicAdd(&g_c1, 1);
        while (*(volatile int*)&g_c1 != NSC) __nanosleep(64);
    }
    __syncthreads();

    __shared__ int run[NCL];
    __shared__ int wc[8][NCL];
    __shared__ int tot_s[NCL], pre_s[NCL];
    if (w < NCL) {
        int c = w, full = 0, pre = 0;
        for (int b = lane; b < NSC; b += 32) {
            int v = g_hist[b*NCL + c];
            full += v;
            if (b < bid) pre += v;
        }
#pragma unroll
        for (int o = 16; o; o >>= 1) {
            full += __shfl_xor_sync(~0u, full, o);
            pre  += __shfl_xor_sync(~0u, pre,  o);
        }
        if (!lane) { tot_s[c] = full; pre_s[c] = pre; }
    }
    __syncthreads();
    if (t == 0) {
        int r = 0;
        for (int k = 0; k < NCL; k++) {
            int o = r; r += tot_s[k];
            run[k] = o + pre_s[k];
            if (bid == 0) { g_coff[k] = o; g_cntf[k] = (float)tot_s[k]; }
        }
        if (bid == 0) g_coff[NCL] = r;
    }
    __syncthreads();

    unsigned ltm = (1u << lane) - 1u;
    for (int q = 0; q < 4; q++) {
        if (t < 80) ((int*)wc)[t] = 0;
        __syncthreads();
        int i = base + q*256 + t;
        int c = (t < 256 && i < NIT) ? cl[i] : -1;
        unsigned mm = __match_any_sync(0xffffffffu, c);
        int myrank = __popc(mm & ltm);
        if (c >= 0 && myrank == 0) wc[w][c] = __popc(mm);
        __syncthreads();
        if (t < NCL) {
            int k = t, s = run[k];
            for (int ww = 0; ww < 8; ww++) { int tmp = wc[ww][k]; wc[ww][k] = s; s += tmp; }
            run[k] = s;
        }
        __syncthreads();
        if (c >= 0) g_dst[i] = wc[w][c] + myrank;
        __syncthreads();
    }
    __threadfence();
    __syncthreads();
    if (t == 0) atomicAdd(&g_c3, 1);
}

// ===========================================================================
// Kernel 2: kmain — cross-chunk pipelined HMMA + anti-phase CTA stagger
// ===========================================================================
__device__ __forceinline__ void stage_B(uint32_t sb, int buf, int ch, int t) {
    uint32_t bh = sb + SM_B0 + buf*16384;
    const char* gh = (const char*)g_W2h + (size_t)ch*CH*128;
#pragma unroll
    for (int q = 0; q < 4; q++) {
        int off = (t + q*256) * 16;
        cpa16(bh + SW128(off), gh + off);
    }
}

// MMA for one 32-item quarter (2 n-tile-pairs) into acc[4][4]
__device__ __forceinline__ void mma_quarter(float (*acc)[4], const uint (*ah)[4],
                                            uint32_t bbh, const int* bx, int q) {
#pragma unroll
    for (int nt = 0; nt < 4; nt++)
#pragma unroll
        for (int j = 0; j < 4; j++) acc[nt][j] = 0.0f;
#pragma unroll
    for (int ks = 0; ks < 4; ks++) {
#pragma unroll
        for (int j = 0; j < 2; j++) {
            uint r[4];
            LDSM4(r, bbh + (2*q + j)*2048 + bx[ks]);
            mma_bf16(acc[2*j],   ah[ks], r[0], r[1]);
            mma_bf16(acc[2*j+1], ah[ks], r[2], r[3]);
        }
    }
}

// exp2 + segment accumulate for one 32-item quarter
__device__ __forceinline__ void epi_quarter(const float (*acc)[4], int p0base, int bpos,
                                            bool fast, int qd,
                                            float& s0a, float& s0b, float& s1a, float& s1b) {
    if (fast) {
        float ta = 0.f, tb = 0.f;
#pragma unroll
        for (int nt = 0; nt < 4; nt++) {
            ta += ex2f(acc[nt][0]); ta += ex2f(acc[nt][1]);
            tb += ex2f(acc[nt][2]); tb += ex2f(acc[nt][3]);
        }
        s0a += ta; s0b += tb;
    } else {
#pragma unroll
        for (int nt = 0; nt < 4; nt++) {
            float e0 = ex2f(acc[nt][0]), e1 = ex2f(acc[nt][1]);
            float e2 = ex2f(acc[nt][2]), e3 = ex2f(acc[nt][3]);
            int p0 = p0base + nt*8 + qd;
            if (p0 < bpos)          { s0a += e0; s0b += e2; }
            else if (p0 < NIT)      { s1a += e0; s1b += e2; }
            if (p0 + 1 < bpos)      { s0a += e1; s0b += e3; }
            else if (p0 + 1 < NIT)  { s1a += e1; s1b += e3; }
        }
    }
}

#define FLUSH_BOUNDARY(ibase_) do {                                          \
    int nc = cur;                                                            \
    while (coff_s[nc+1] <= (ibase_)) nc++;                                   \
    if (nc != cur) {                                                         \
        atomicAdd(&g_sums[row0*NCL + cur], s0a);                             \
        atomicAdd(&g_sums[row1*NCL + cur], s0b);                             \
        if (cur + 1 < NCL) {                                                 \
            atomicAdd(&g_sums[row0*NCL + cur + 1], s1a);                     \
            atomicAdd(&g_sums[row1*NCL + cur + 1], s1b);                     \
        }                                                                    \
        s0a = s0b = s1a = s1b = 0.f;                                         \
        cur = nc;                                                            \
    }                                                                        \
} while (0)

// steady-state pipelined step: A,B hold pending q2/q3 of previous chunk
#define STEP(A_, B_, C_, II) do {                                            \
    if ((II) + 1 < n) { stage_B(sb, ((II)+1)&1, ch_lo + (II) + 1, t);        \
                        CPA_COMMIT(); CPA_WAIT1(); }                         \
    else              { CPA_WAIT0(); }                                       \
    __syncthreads();                                                         \
    uint32_t bbh = sb + SM_B0 + ((II)&1)*16384;                              \
    int ibase = (ch_lo + (II)) * CH;                                         \
    mma_quarter(C_, ah, bbh, bx, 0);                                         \
    epi_quarter(A_, prev_ibase + 64, prev_bpos, prev_fast, qd, s0a,s0b,s1a,s1b); \
    mma_quarter(A_, ah, bbh, bx, 1);                                         \
    epi_quarter(B_, prev_ibase + 96, prev_bpos, prev_fast, qd, s0a,s0b,s1a,s1b); \
    FLUSH_BOUNDARY(ibase);                                                   \
    int bpos = coff_s[cur+1];                                                \
    bool fast = (ibase + CH <= bpos);                                        \
    mma_quarter(B_, ah, bbh, bx, 2);                                         \
    epi_quarter(C_, ibase, bpos, fast, qd, s0a,s0b,s1a,s1b);                 \
    mma_quarter(C_, ah, bbh, bx, 3);                                         \
    epi_quarter(A_, ibase + 32, bpos, fast, qd, s0a,s0b,s1a,s1b);            \
    prev_ibase = ibase; prev_bpos = bpos; prev_fast = fast;                  \
    __syncthreads();                                                         \
} while (0)

__global__ void __launch_bounds__(256, 2) kmain(float* __restrict__ out) {
    extern __shared__ char dsm[];
    __shared__ int coff_s[NCL+1];
    __shared__ int slast;
    uint32_t sb0 = smem_u32(dsm);
    uint32_t pad = (1024u - (sb0 & 1023u)) & 1023u;
    uint32_t sb  = sb0 + pad;

    int t = threadIdx.x, lane = t & 31, w = t >> 5;
    int bbase = blockIdx.x * BT;
    int ch_lo = (blockIdx.y * NCH) / NS;          // balanced 21-22 chunk ranges
    int ch_hi = ((blockIdx.y + 1) * NCH) / NS;
    int n = ch_hi - ch_lo;

    // anti-phase stagger: second wave-slot member of each same-SM CTA pair
    // delays ~half a chunk so its MUFU burst overlaps the partner's MMA burst.
    {
        int bidlin = blockIdx.x + (int)gridDim.x * blockIdx.y;
        if (bidlin >= 148) { __nanosleep(320); __nanosleep(320); }
    }

    if (t < NCL+1) coff_s[t] = g_coff[t];

    // stage A (Hh, 16 KB, SW128) + first B chunk
    {
        const char* gh = (const char*)g_Hh + (size_t)bbase*128;
#pragma unroll
        for (int q = 0; q < 4; q++) {
            int off = (t + q*256) * 16;
            cpa16(sb + SM_AH + SW128(off), gh + off);
        }
    }
    stage_B(sb, 0, ch_lo, t);
    CPA_COMMIT();
    CPA_WAIT0();
    __syncthreads();

    // per-lane ldmatrix B address precompute
    int m  = lane >> 3, rl = lane & 7;
    int rowb = ((m >> 1) << 3) + rl;
    int kadd = m & 1;
    int bx[4];
#pragma unroll
    for (int ks = 0; ks < 4; ks++)
        bx[ks] = rowb*128 + ((ks*32 + kadd*16) ^ (rl*16));

    // A fragments resident in registers for the whole kernel
    uint ah[4][4];
    {
        int arow = w*16 + ((lane >> 3) & 1)*8 + rl;
#pragma unroll
        for (int ks = 0; ks < 4; ks++) {
            int au   = ks*2 + (lane >> 4);
            int aoff = arow*128 + ((au*16) ^ (rl*16));
            LDSM4(ah[ks], sb + SM_AH + aoff);
        }
    }

    int row0 = bbase + w*16 + (lane >> 2);
    int row1 = row0 + 8;
    int qd   = (lane & 3) * 2;
    float s0a = 0.f, s0b = 0.f, s1a = 0.f, s1b = 0.f;
    int cur = 0;
    { int ib = ch_lo * CH; while (coff_s[cur+1] <= ib) cur++; }

    float acc0[4][4], acc1[4][4], acc2[4][4];
    int prev_ibase, prev_bpos;
    bool prev_fast;

    // ---- iteration 0 (no pending epilogues) ----
    {
        if (1 < n) { stage_B(sb, 1, ch_lo + 1, t); CPA_COMMIT(); CPA_WAIT1(); }
        else       { CPA_WAIT0(); }
        __syncthreads();
        uint32_t bbh = sb + SM_B0;
        int ibase = ch_lo * CH;
        FLUSH_BOUNDARY(ibase);
        int bpos = coff_s[cur+1];
        bool fast = (ibase + CH <= bpos);
        mma_quarter(acc2, ah, bbh, bx, 0);
        mma_quarter(acc0, ah, bbh, bx, 1);
        mma_quarter(acc1, ah, bbh, bx, 2);
        epi_quarter(acc2, ibase, bpos, fast, qd, s0a,s0b,s1a,s1b);        // q0
        mma_quarter(acc2, ah, bbh, bx, 3);                                // q3 -> acc2
        epi_quarter(acc0, ibase + 32, bpos, fast, qd, s0a,s0b,s1a,s1b);   // q1
        prev_ibase = ibase; prev_bpos = bpos; prev_fast = fast;
        __syncthreads();
        // pending: acc1(q2), acc2(q3); free acc0
    }

    // ---- steady state: rotate slots (period 3) ----
    {
        int ii = 1;
        while (ii < n) {
            STEP(acc1, acc2, acc0, ii); ii++;     // -> pending acc2, acc0
            if (ii >= n) break;
            STEP(acc2, acc0, acc1, ii); ii++;     // -> pending acc0, acc1
            if (ii >= n) break;
            STEP(acc0, acc1, acc2, ii); ii++;     // -> pending acc1, acc2
        }
    }

    // ---- drain pending epilogues of the last chunk ----
    {
        int r = (n - 1) % 3;   // number of steps mod 3
        if (r == 0) {
            epi_quarter(acc1, prev_ibase + 64, prev_bpos, prev_fast, qd, s0a,s0b,s1a,s1b);
            epi_quarter(acc2, prev_ibase + 96, prev_bpos, prev_fast, qd, s0a,s0b,s1a,s1b);
        } else if (r == 1) {
            epi_quarter(acc2, prev_ibase + 64, prev_bpos, prev_fast, qd, s0a,s0b,s1a,s1b);
            epi_quarter(acc0, prev_ibase + 96, prev_bpos, prev_fast, qd, s0a,s0b,s1a,s1b);
        } else {
            epi_quarter(acc0, prev_ibase + 64, prev_bpos, prev_fast, qd, s0a,s0b,s1a,s1b);
            epi_quarter(acc1, prev_ibase + 96, prev_bpos, prev_fast, qd, s0a,s0b,s1a,s1b);
        }
    }

    atomicAdd(&g_sums[row0*NCL + cur], s0a);
    atomicAdd(&g_sums[row1*NCL + cur], s0b);
    if (cur + 1 < NCL) {
        atomicAdd(&g_sums[row0*NCL + cur + 1], s1a);
        atomicAdd(&g_sums[row1*NCL + cur + 1], s1b);
    }

    // ---- fused finalize: last CTA computes output + restores scratch -----
    __threadfence();
    __syncthreads();
    if (t == 0) slast = (atomicAdd(&g_c2, 1) == (int)(gridDim.x*gridDim.y) - 1);
    __syncthreads();
    if (slast) {
        __threadfence();
        for (int b = t; b < NB; b += 256) {
            float v[NCL], z = 0.0f;
#pragma unroll
            for (int c = 0; c < NCL; c++) { v[c] = g_sums[b*NCL + c]; z += v[c]; }
            float invz = 1.0f / z;
#pragma unroll
            for (int c = 0; c < NCL; c++)
                out[b*NCL + c] = v[c] * invz / fmaxf(g_cntf[c], 1.0f);
#pragma unroll
            for (int c = 0; c < NCL; c++) g_sums[b*NCL + c] = 0.0f;
        }
        for (int i = t; i < NCL*DD; i += 256) g_G1[i] = 0.0f;
        if (t == 0) { g_c1 = 0; g_c2 = 0; g_c3 = 0; g_c4 = 0; }
    }
}

// ---------------------------------------------------------------------------
extern "C" void kernel_launch(void* const* d_in, const int* in_sizes, int n_in,
                              void* d_out, int out_size) {
    const float* input = (const float*)d_in[0];   // (1024, 10) f32
    const int*   clust = (const int*)d_in[1];     // (100000,) i32
    const float* W1    = (const float*)d_in[2];   // (100000, 64) f32
    const float* W2    = (const float*)d_in[3];   // (64, 100000) f32
    float*       out   = (float*)d_out;           // (1024, 10) f32

    cudaFuncSetAttribute(kmain, cudaFuncAttributeMaxDynamicSharedMemorySize, SMEM_KM);
    cudaFuncSetAttribute(kprep, cudaFuncAttributeMaxDynamicSharedMemorySize, SMEM_KP);

    kprep<<<NSC + GB + HB + PB, 320, SMEM_KP>>>(clust, W1, W2, input);
    dim3 grid(NB / BT, NS);
    kmain<<<grid, 256, SMEM_KM>>>(out);
}